// round 2
// baseline (speedup 1.0000x reference)
#include <cuda_runtime.h>
#include <cuda_bf16.h>
#include <math.h>

// Problem constants
#define BB   16
#define NC   1024
#define NF   4096
#define CC   256
#define KNN  3
#define MM   (BB * NF)      // 65536 fine points

// Scratch (allocation-free rule: __device__ globals)
__device__ float g_H0[MM * 512];   // [M, 512] concat(interp, x_skip)
__device__ float g_H1[MM * 512];   // [M, 512] relu(H0 @ W1 + b1)
__device__ int   g_idx[MM * KNN];
__device__ float g_w[MM * KNN];    // normalized weights

// ---------------------------------------------------------------------------
// KNN: for each fine point find 3 nearest coarse points (same batch),
// store global gather indices and normalized inverse-sq-dist weights.
// grid: MM/256 blocks, 256 threads. All points in a block share one batch.
// ---------------------------------------------------------------------------
__global__ void knn_kernel(const float* __restrict__ pos_c,
                           const float* __restrict__ pos_f) {
    __shared__ float4 sp[NC];
    int i = blockIdx.x * 256 + threadIdx.x;     // fine point index
    int b = i >> 12;                            // / NF
    const float* pc = pos_c + (size_t)b * NC * 3;
    for (int t = threadIdx.x; t < NC; t += 256) {
        sp[t] = make_float4(pc[t * 3 + 0], pc[t * 3 + 1], pc[t * 3 + 2], 0.0f);
    }
    __syncthreads();

    float px = pos_f[i * 3 + 0];
    float py = pos_f[i * 3 + 1];
    float pz = pos_f[i * 3 + 2];

    float d0 = INFINITY, d1 = INFINITY, d2 = INFINITY;
    int   i0 = 0, i1 = 0, i2 = 0;

    #pragma unroll 4
    for (int j = 0; j < NC; j++) {
        float4 p = sp[j];
        float dx = px - p.x, dy = py - p.y, dz = pz - p.z;
        float d = dx * dx + dy * dy + dz * dz;
        if (d < d2) {
            if (d < d1) {
                if (d < d0) {
                    d2 = d1; i2 = i1;
                    d1 = d0; i1 = i0;
                    d0 = d;  i0 = j;
                } else {
                    d2 = d1; i2 = i1;
                    d1 = d;  i1 = j;
                }
            } else {
                d2 = d; i2 = j;
            }
        }
    }

    float w0 = 1.0f / (d0 + 1e-16f);
    float w1 = 1.0f / (d1 + 1e-16f);
    float w2 = 1.0f / (d2 + 1e-16f);
    float inv = 1.0f / (w0 + w1 + w2);

    int base = b * NC;
    g_idx[i * 3 + 0] = base + i0;
    g_idx[i * 3 + 1] = base + i1;
    g_idx[i * 3 + 2] = base + i2;
    g_w[i * 3 + 0] = w0 * inv;
    g_w[i * 3 + 1] = w1 * inv;
    g_w[i * 3 + 2] = w2 * inv;
}

// ---------------------------------------------------------------------------
// Interp + concat: H0[i, 0:256]   = sum_k w_k * feats[idx_k, :]
//                  H0[i, 256:512] = x_skip[i, :]
// grid: MM/4 blocks, 256 threads: each warp-pair (64 threads) does one row
// with float4 channels (256 ch / 64 thr = 1 float4 per thread).
// ---------------------------------------------------------------------------
__global__ void interp_kernel(const float* __restrict__ feats,
                              const float* __restrict__ x_skip) {
    int i = blockIdx.x * 4 + (threadIdx.x >> 6);   // row
    int c4 = (threadIdx.x & 63);                   // float4 lane 0..63
    int j0 = g_idx[i * 3 + 0];
    int j1 = g_idx[i * 3 + 1];
    int j2 = g_idx[i * 3 + 2];
    float w0 = g_w[i * 3 + 0];
    float w1 = g_w[i * 3 + 1];
    float w2 = g_w[i * 3 + 2];

    float4 f0 = *(const float4*)(feats + (size_t)j0 * CC + c4 * 4);
    float4 f1 = *(const float4*)(feats + (size_t)j1 * CC + c4 * 4);
    float4 f2 = *(const float4*)(feats + (size_t)j2 * CC + c4 * 4);
    float4 v;
    v.x = w0 * f0.x + w1 * f1.x + w2 * f2.x;
    v.y = w0 * f0.y + w1 * f1.y + w2 * f2.y;
    v.z = w0 * f0.z + w1 * f1.z + w2 * f2.z;
    v.w = w0 * f0.w + w1 * f1.w + w2 * f2.w;

    *(float4*)(g_H0 + (size_t)i * 512 + c4 * 4) = v;
    *(float4*)(g_H0 + (size_t)i * 512 + 256 + c4 * 4) =
        *(const float4*)(x_skip + (size_t)i * CC + c4 * 4);
}

// ---------------------------------------------------------------------------
// Tiled fp32 GEMM with fused bias + ReLU.  C[M,N] = relu(A[M,K] @ B[K,N] + b)
// BM=128, BN=128, BK=16, 256 threads, 8x8 register tile per thread.
// M % 128 == 0, N % 128 == 0, K % 16 == 0 (true here).
// ---------------------------------------------------------------------------
__global__ __launch_bounds__(256)
void gemm_bias_relu(const float* __restrict__ A, const float* __restrict__ Bm,
                    const float* __restrict__ bias, float* __restrict__ Cm,
                    int M, int N, int K) {
    const int BM = 128, BN = 128, BK = 16, TM = 8, TN = 8;
    __shared__ float As[BK][BM];      // transposed A tile
    __shared__ float Bs[BK][BN];

    int tid  = threadIdx.x;
    int bm   = blockIdx.y * BM;
    int bn   = blockIdx.x * BN;
    int tcol = tid & 15;              // 0..15  (BN/TN = 16)
    int trow = tid >> 4;              // 0..15  (BM/TM = 16)

    float acc[TM][TN];
    #pragma unroll
    for (int m = 0; m < TM; m++)
        #pragma unroll
        for (int n = 0; n < TN; n++) acc[m][n] = 0.0f;

    for (int k0 = 0; k0 < K; k0 += BK) {
        // Load A tile: 128x16 floats = 512 float4, 2 per thread (transpose)
        #pragma unroll
        for (int l = 0; l < 2; l++) {
            int idx4 = tid + l * 256;
            int r  = idx4 >> 2;          // 0..127
            int c4 = (idx4 & 3) << 2;    // 0,4,8,12
            float4 v = *(const float4*)(A + (size_t)(bm + r) * K + k0 + c4);
            As[c4 + 0][r] = v.x;
            As[c4 + 1][r] = v.y;
            As[c4 + 2][r] = v.z;
            As[c4 + 3][r] = v.w;
        }
        // Load B tile: 16x128 floats = 512 float4, 2 per thread
        #pragma unroll
        for (int l = 0; l < 2; l++) {
            int idx4 = tid + l * 256;
            int r  = idx4 >> 5;          // 0..15
            int c4 = (idx4 & 31) << 2;   // 0..124
            *(float4*)(&Bs[r][c4]) =
                *(const float4*)(Bm + (size_t)(k0 + r) * N + bn + c4);
        }
        __syncthreads();

        #pragma unroll
        for (int kk = 0; kk < BK; kk++) {
            float af[TM], bf[TN];
            #pragma unroll
            for (int m = 0; m < TM; m += 4) {
                float4 v = *(const float4*)(&As[kk][trow * TM + m]);
                af[m + 0] = v.x; af[m + 1] = v.y; af[m + 2] = v.z; af[m + 3] = v.w;
            }
            #pragma unroll
            for (int n = 0; n < TN; n += 4) {
                float4 v = *(const float4*)(&Bs[kk][tcol * TN + n]);
                bf[n + 0] = v.x; bf[n + 1] = v.y; bf[n + 2] = v.z; bf[n + 3] = v.w;
            }
            #pragma unroll
            for (int m = 0; m < TM; m++)
                #pragma unroll
                for (int n = 0; n < TN; n++)
                    acc[m][n] += af[m] * bf[n];
        }
        __syncthreads();
    }

    // Epilogue: bias + ReLU, vectorized store
    float bv[TN];
    #pragma unroll
    for (int n = 0; n < TN; n += 4) {
        float4 v = *(const float4*)(bias + bn + tcol * TN + n);
        bv[n + 0] = v.x; bv[n + 1] = v.y; bv[n + 2] = v.z; bv[n + 3] = v.w;
    }
    #pragma unroll
    for (int m = 0; m < TM; m++) {
        int row = bm + trow * TM + m;
        #pragma unroll
        for (int n = 0; n < TN; n += 4) {
            float4 o;
            o.x = fmaxf(acc[m][n + 0] + bv[n + 0], 0.0f);
            o.y = fmaxf(acc[m][n + 1] + bv[n + 1], 0.0f);
            o.z = fmaxf(acc[m][n + 2] + bv[n + 2], 0.0f);
            o.w = fmaxf(acc[m][n + 3] + bv[n + 3], 0.0f);
            *(float4*)(Cm + (size_t)row * N + bn + tcol * TN + n) = o;
        }
    }
}

// ---------------------------------------------------------------------------
// Tail: copy pos_skip (float) and batch_skip (int -> float) to output tail.
// ---------------------------------------------------------------------------
__global__ void tail_kernel(const float* __restrict__ pos_skip,
                            const int* __restrict__ batch_skip,
                            float* __restrict__ out) {
    int t = blockIdx.x * 256 + threadIdx.x;
    const size_t POS_OFF = (size_t)MM * CC;              // 16777216
    const size_t BAT_OFF = POS_OFF + (size_t)MM * 3;     // +196608
    if (t < MM * 3) out[POS_OFF + t] = pos_skip[t];
    if (t < MM)     out[BAT_OFF + t] = (float)batch_skip[t];
}

// ---------------------------------------------------------------------------
extern "C" void kernel_launch(void* const* d_in, const int* in_sizes, int n_in,
                              void* d_out, int out_size) {
    const float* x          = (const float*)d_in[0];   // [B*NC, 256]
    const float* pos        = (const float*)d_in[1];   // [B*NC, 3]
    // d_in[2] = batch (unused; contiguous equal batches)
    const float* x_skip     = (const float*)d_in[3];   // [B*NF, 256]
    const float* pos_skip   = (const float*)d_in[4];   // [B*NF, 3]
    const int*   batch_skip = (const int*)d_in[5];     // [B*NF]
    const float* W1         = (const float*)d_in[6];   // [512, 512]
    const float* b1         = (const float*)d_in[7];   // [512]
    const float* W2         = (const float*)d_in[8];   // [512, 256]
    const float* b2         = (const float*)d_in[9];   // [256]
    float* out = (float*)d_out;

    float* H0;  cudaGetSymbolAddress((void**)&H0, g_H0);
    float* H1;  cudaGetSymbolAddress((void**)&H1, g_H1);

    // 1) 3-NN search
    knn_kernel<<<MM / 256, 256>>>(pos, pos_skip);

    // 2) interpolation + concat into H0 [M, 512]
    interp_kernel<<<MM / 4, 256>>>(x, x_skip);

    // 3) H1 = relu(H0 @ W1 + b1)   [65536 x 512]
    {
        dim3 grid(512 / 128, MM / 128);
        gemm_bias_relu<<<grid, 256>>>(H0, W1, b1, H1, MM, 512, 512);
    }

    // 4) h = relu(H1 @ W2 + b2)    [65536 x 256] -> d_out head
    {
        dim3 grid(256 / 128, MM / 128);
        gemm_bias_relu<<<grid, 256>>>(H1, W2, b2, out, MM, 256, 512);
    }

    // 5) tail outputs (pos_skip, batch_skip) if the output buffer includes them
    const long long FULL = (long long)MM * CC + (long long)MM * 3 + MM;
    if ((long long)out_size >= FULL) {
        tail_kernel<<<(MM * 3 + 255) / 256, 256>>>(pos_skip, batch_skip, out);
    }
}

// round 4
// speedup vs baseline: 1.9319x; 1.9319x over previous
#include <cuda_runtime.h>
#include <cuda_fp16.h>
#include <math.h>
#include <stdint.h>

// ---------------------------------------------------------------- constants
#define BB   16
#define NC   1024
#define NF   4096
#define CC   256
#define MM   (BB * NF)      // 65536 fine points
#define MC   (BB * NC)      // 16384 coarse points

// ---------------------------------------------------------------- scratch
__device__ __align__(16) __half g_Xhi[MC * 256];       // x split
__device__ __align__(16) __half g_Xlo[MC * 256];
__device__ __align__(16) __half g_Shi[MM * 256];       // x_skip split
__device__ __align__(16) __half g_Slo[MM * 256];
__device__ __align__(16) __half g_H1hi[MM * 512];      // layer1 out split
__device__ __align__(16) __half g_H1lo[MM * 512];
__device__ __align__(16) float  g_Z[MC * 512];         // x @ W1a (fp32)
__device__ __align__(16) __half g_W1aThi[512 * 256];   // [N=512][K=256]
__device__ __align__(16) __half g_W1aTlo[512 * 256];
__device__ __align__(16) __half g_W1bThi[512 * 256];
__device__ __align__(16) __half g_W1bTlo[512 * 256];
__device__ __align__(16) __half g_W2Thi[256 * 512];    // [N=256][K=512]
__device__ __align__(16) __half g_W2Tlo[256 * 512];
__device__ int   g_idx[MM * 3];
__device__ float g_w[MM * 3];

// ---------------------------------------------------------------- helpers
__device__ __forceinline__ uint32_t smem_u32(const void* p) {
    uint32_t a;
    asm("{ .reg .u64 t; cvta.to.shared.u64 t, %1; cvt.u32.u64 %0, t; }"
        : "=r"(a) : "l"(p));
    return a;
}
__device__ __forceinline__ void cp16(uint32_t dst, const void* src) {
    asm volatile("cp.async.cg.shared.global [%0], [%1], 16;" :: "r"(dst), "l"(src));
}
__device__ __forceinline__ void ldsm4(uint32_t* r, uint32_t addr) {
    asm volatile("ldmatrix.sync.aligned.m8n8.x4.shared.b16 {%0,%1,%2,%3}, [%4];"
        : "=r"(r[0]), "=r"(r[1]), "=r"(r[2]), "=r"(r[3]) : "r"(addr));
}
__device__ __forceinline__ void mma16816(float* d, const uint32_t* a, const uint32_t* b) {
    asm volatile("mma.sync.aligned.m16n8k16.row.col.f32.f16.f16.f32 "
        "{%0,%1,%2,%3}, {%4,%5,%6,%7}, {%8,%9}, {%0,%1,%2,%3};"
        : "+f"(d[0]), "+f"(d[1]), "+f"(d[2]), "+f"(d[3])
        : "r"(a[0]), "r"(a[1]), "r"(a[2]), "r"(a[3]), "r"(b[0]), "r"(b[1]));
}
__device__ __forceinline__ void split_h(float v, __half& h, __half& l) {
    h = __float2half_rn(v);
    l = __float2half_rn(v - __half2float(h));
}

// ---------------------------------------------------------------- KNN (unchanged, validated)
__global__ void knn_kernel(const float* __restrict__ pos_c,
                           const float* __restrict__ pos_f) {
    __shared__ float4 sp[NC];
    int i = blockIdx.x * 256 + threadIdx.x;
    int b = i >> 12;
    const float* pc = pos_c + (size_t)b * NC * 3;
    for (int t = threadIdx.x; t < NC; t += 256)
        sp[t] = make_float4(pc[t * 3 + 0], pc[t * 3 + 1], pc[t * 3 + 2], 0.0f);
    __syncthreads();

    float px = pos_f[i * 3 + 0], py = pos_f[i * 3 + 1], pz = pos_f[i * 3 + 2];
    float d0 = INFINITY, d1 = INFINITY, d2 = INFINITY;
    int   i0 = 0, i1 = 0, i2 = 0;
    #pragma unroll 4
    for (int j = 0; j < NC; j++) {
        float4 p = sp[j];
        float dx = px - p.x, dy = py - p.y, dz = pz - p.z;
        float d = dx * dx + dy * dy + dz * dz;
        if (d < d2) {
            if (d < d1) {
                if (d < d0) { d2 = d1; i2 = i1; d1 = d0; i1 = i0; d0 = d; i0 = j; }
                else        { d2 = d1; i2 = i1; d1 = d;  i1 = j; }
            } else          { d2 = d;  i2 = j; }
        }
    }
    float w0 = 1.0f / (d0 + 1e-16f), w1 = 1.0f / (d1 + 1e-16f), w2 = 1.0f / (d2 + 1e-16f);
    float inv = 1.0f / (w0 + w1 + w2);
    int base = b * NC;
    g_idx[i * 3 + 0] = base + i0;  g_idx[i * 3 + 1] = base + i1;  g_idx[i * 3 + 2] = base + i2;
    g_w[i * 3 + 0] = w0 * inv;     g_w[i * 3 + 1] = w1 * inv;     g_w[i * 3 + 2] = w2 * inv;
}

// ---------------------------------------------------------------- fp32 -> fp16 hi/lo split
__global__ void split_kernel(const float* __restrict__ in,
                             __half* __restrict__ hi, __half* __restrict__ lo) {
    int t = blockIdx.x * 256 + threadIdx.x;        // float4 index
    float4 v = ((const float4*)in)[t];
    __half h[4], l[4];
    split_h(v.x, h[0], l[0]);  split_h(v.y, h[1], l[1]);
    split_h(v.z, h[2], l[2]);  split_h(v.w, h[3], l[3]);
    ((uint2*)hi)[t] = *(uint2*)h;
    ((uint2*)lo)[t] = *(uint2*)l;
}

// ---------------------------------------------------------------- weight transpose + split
// in: [Kt rows][N cols] fp32 -> out [N][Kt] fp16 hi/lo
__global__ void transpose_split(const float* __restrict__ in, int N, int Kt,
                                __half* __restrict__ oh, __half* __restrict__ ol) {
    __shared__ float t[32][33];
    int n0 = blockIdx.x * 32, k0 = blockIdx.y * 32;
    int xx = threadIdx.x;
    for (int j = threadIdx.y; j < 32; j += 8)
        t[j][xx] = in[(size_t)(k0 + j) * N + n0 + xx];
    __syncthreads();
    for (int j = threadIdx.y; j < 32; j += 8) {
        __half h, l;
        split_h(t[xx][j], h, l);
        size_t o = (size_t)(n0 + j) * Kt + k0 + xx;
        oh[o] = h;  ol[o] = l;
    }
}

// ---------------------------------------------------------------- mma.sync GEMM
// C[128x128 per CTA] = (Ahi+Alo)[M,K] @ (Bhi+Blo)^T[N,K]   (3-term fp16 split)
// MODE 0: C -> fp32 (no bias/relu)                 [Z = x @ W1a]
// MODE 1: relu(C + bias + Sum w_k Z[idx_k]) -> fp16 hi/lo   [layer 1]
// MODE 2: relu(C + bias) -> fp32                   [layer 2 -> d_out]
#define TILE_B  10240                 // 128 rows * 80B (padded: 32 fp16 in 40)
#define STG_B   (4 * TILE_B)          // Ahi, Alo, Bhi, Blo
#define NSTG    3
#define GEMM_SMEM (NSTG * STG_B)      // 122880

template<int MODE>
__global__ __launch_bounds__(256, 1)
void gemm_mma(const __half* __restrict__ Ahi, const __half* __restrict__ Alo,
              const __half* __restrict__ Bhi, const __half* __restrict__ Blo,
              const float* __restrict__ bias, const float* __restrict__ Zt,
              float* __restrict__ outF,
              __half* __restrict__ outHi, __half* __restrict__ outLo,
              int K, int ldout) {
    extern __shared__ __align__(128) char smem[];
    const uint32_t sbase = smem_u32(smem);
    const int tid  = threadIdx.x;
    const int wid  = tid >> 5, lane = tid & 31;
    const int wm   = (wid >> 2) * 64;          // warp M offset (0/64)
    const int wn   = (wid & 3) * 32;           // warp N offset
    const int bm   = blockIdx.y * 128, bn = blockIdx.x * 128;
    const int KT   = K >> 5;                   // BK=32 tiles

    // cp.async source/dest decomposition (2 chunk-groups per thread per array)
    const int r0s = tid >> 2, q0s = tid & 3;           // seg = tid
    const int r1s = (tid + 256) >> 2, q1s = tid & 3;   // seg = tid + 256

    auto load_tile = [&](int kt, int stg) {
        const uint32_t sb = sbase + stg * STG_B;
        const size_t ka = (size_t)kt * 32;
        {   // group 0
            size_t ar = (size_t)(bm + r0s) * K + ka + q0s * 8;
            size_t br = (size_t)(bn + r0s) * K + ka + q0s * 8;
            uint32_t d = r0s * 80 + q0s * 16;
            cp16(sb + d,              Ahi + ar);
            cp16(sb + TILE_B + d,     Alo + ar);
            cp16(sb + 2 * TILE_B + d, Bhi + br);
            cp16(sb + 3 * TILE_B + d, Blo + br);
        }
        {   // group 1
            size_t ar = (size_t)(bm + r1s) * K + ka + q1s * 8;
            size_t br = (size_t)(bn + r1s) * K + ka + q1s * 8;
            uint32_t d = r1s * 80 + q1s * 16;
            cp16(sb + d,              Ahi + ar);
            cp16(sb + TILE_B + d,     Alo + ar);
            cp16(sb + 2 * TILE_B + d, Bhi + br);
            cp16(sb + 3 * TILE_B + d, Blo + br);
        }
        asm volatile("cp.async.commit_group;" ::: "memory");
    };

    float acc[4][4][4];
    #pragma unroll
    for (int a = 0; a < 4; a++)
        #pragma unroll
        for (int b = 0; b < 4; b++)
            #pragma unroll
            for (int c = 0; c < 4; c++) acc[a][b][c] = 0.0f;

    // ldmatrix per-lane address components
    const int lmr = (lane & 7) + ((lane >> 3) & 1) * 8;   // row within 16-row tile
    const int lmc = (lane >> 4) & 1;                       // k8 half

    // prefetch NSTG-1 stages
    load_tile(0, 0);
    load_tile(1, 1);

    for (int kt = 0; kt < KT; kt++) {
        asm volatile("cp.async.wait_group 1;" ::: "memory");
        __syncthreads();
        if (kt + 2 < KT) load_tile(kt + 2, (kt + 2) % NSTG);

        const uint32_t sb   = sbase + (kt % NSTG) * STG_B;
        const uint32_t aOff = sb + (wm + lmr) * 80 + lmc * 16;
        const uint32_t bOff = sb + 2 * TILE_B + (wn + lmr) * 80 + lmc * 16;

        #pragma unroll
        for (int kc = 0; kc < 2; kc++) {
            uint32_t aH[4][4], aL[4][4], bH[4][2], bL[4][2];
            #pragma unroll
            for (int mt = 0; mt < 4; mt++) {
                ldsm4(aH[mt], aOff + mt * 16 * 80 + kc * 32);
                ldsm4(aL[mt], aOff + TILE_B + mt * 16 * 80 + kc * 32);
            }
            #pragma unroll
            for (int bt = 0; bt < 2; bt++) {
                uint32_t t4[4];
                ldsm4(t4, bOff + bt * 16 * 80 + kc * 32);
                bH[bt * 2][0] = t4[0]; bH[bt * 2][1] = t4[2];
                bH[bt * 2 + 1][0] = t4[1]; bH[bt * 2 + 1][1] = t4[3];
                ldsm4(t4, bOff + TILE_B + bt * 16 * 80 + kc * 32);
                bL[bt * 2][0] = t4[0]; bL[bt * 2][1] = t4[2];
                bL[bt * 2 + 1][0] = t4[1]; bL[bt * 2 + 1][1] = t4[3];
            }
            // 3-term split accumulation (16 independent tiles between deps)
            #pragma unroll
            for (int mt = 0; mt < 4; mt++)
                #pragma unroll
                for (int nt = 0; nt < 4; nt++)
                    mma16816(acc[mt][nt], aH[mt], bH[nt]);
            #pragma unroll
            for (int mt = 0; mt < 4; mt++)
                #pragma unroll
                for (int nt = 0; nt < 4; nt++)
                    mma16816(acc[mt][nt], aH[mt], bL[nt]);
            #pragma unroll
            for (int mt = 0; mt < 4; mt++)
                #pragma unroll
                for (int nt = 0; nt < 4; nt++)
                    mma16816(acc[mt][nt], aL[mt], bH[nt]);
        }
    }

    // ---------------- epilogue ----------------
    #pragma unroll
    for (int mt = 0; mt < 4; mt++) {
        int r0 = bm + wm + mt * 16 + (lane >> 2);
        int r1 = r0 + 8;
        int   ja0 = 0, ja1 = 0, ja2 = 0, jb0 = 0, jb1 = 0, jb2 = 0;
        float wa0 = 0, wa1 = 0, wa2 = 0, wb0 = 0, wb1 = 0, wb2 = 0;
        if (MODE == 1) {
            ja0 = g_idx[r0 * 3 + 0]; ja1 = g_idx[r0 * 3 + 1]; ja2 = g_idx[r0 * 3 + 2];
            wa0 = g_w[r0 * 3 + 0];   wa1 = g_w[r0 * 3 + 1];   wa2 = g_w[r0 * 3 + 2];
            jb0 = g_idx[r1 * 3 + 0]; jb1 = g_idx[r1 * 3 + 1]; jb2 = g_idx[r1 * 3 + 2];
            wb0 = g_w[r1 * 3 + 0];   wb1 = g_w[r1 * 3 + 1];   wb2 = g_w[r1 * 3 + 2];
        }
        #pragma unroll
        for (int nt = 0; nt < 4; nt++) {
            int c = bn + wn + nt * 8 + (lane & 3) * 2;
            float v0 = acc[mt][nt][0], v1 = acc[mt][nt][1];
            float v2 = acc[mt][nt][2], v3 = acc[mt][nt][3];
            if (MODE != 0) {
                float2 bv = *(const float2*)(bias + c);
                v0 += bv.x; v1 += bv.y; v2 += bv.x; v3 += bv.y;
            }
            if (MODE == 1) {
                float2 z;
                z = *(const float2*)(Zt + (size_t)ja0 * 512 + c); v0 += wa0 * z.x; v1 += wa0 * z.y;
                z = *(const float2*)(Zt + (size_t)ja1 * 512 + c); v0 += wa1 * z.x; v1 += wa1 * z.y;
                z = *(const float2*)(Zt + (size_t)ja2 * 512 + c); v0 += wa2 * z.x; v1 += wa2 * z.y;
                z = *(const float2*)(Zt + (size_t)jb0 * 512 + c); v2 += wb0 * z.x; v3 += wb0 * z.y;
                z = *(const float2*)(Zt + (size_t)jb1 * 512 + c); v2 += wb1 * z.x; v3 += wb1 * z.y;
                z = *(const float2*)(Zt + (size_t)jb2 * 512 + c); v2 += wb2 * z.x; v3 += wb2 * z.y;
            }
            if (MODE != 0) {
                v0 = fmaxf(v0, 0.0f); v1 = fmaxf(v1, 0.0f);
                v2 = fmaxf(v2, 0.0f); v3 = fmaxf(v3, 0.0f);
            }
            if (MODE == 1) {
                __half h0, l0, h1, l1;
                split_h(v0, h0, l0); split_h(v1, h1, l1);
                *(__half2*)(outHi + (size_t)r0 * ldout + c) = __halves2half2(h0, h1);
                *(__half2*)(outLo + (size_t)r0 * ldout + c) = __halves2half2(l0, l1);
                split_h(v2, h0, l0); split_h(v3, h1, l1);
                *(__half2*)(outHi + (size_t)r1 * ldout + c) = __halves2half2(h0, h1);
                *(__half2*)(outLo + (size_t)r1 * ldout + c) = __halves2half2(l0, l1);
            } else {
                *(float2*)(outF + (size_t)r0 * ldout + c) = make_float2(v0, v1);
                *(float2*)(outF + (size_t)r1 * ldout + c) = make_float2(v2, v3);
            }
        }
    }
}

// ---------------------------------------------------------------- tail
__global__ void tail_kernel(const float* __restrict__ pos_skip,
                            const int* __restrict__ batch_skip,
                            float* __restrict__ out) {
    int t = blockIdx.x * 256 + threadIdx.x;
    const size_t POS_OFF = (size_t)MM * CC;
    const size_t BAT_OFF = POS_OFF + (size_t)MM * 3;
    if (t < MM * 3) out[POS_OFF + t] = pos_skip[t];
    if (t < MM)     out[BAT_OFF + t] = (float)batch_skip[t];
}

// ---------------------------------------------------------------- launch
extern "C" void kernel_launch(void* const* d_in, const int* in_sizes, int n_in,
                              void* d_out, int out_size) {
    const float* x          = (const float*)d_in[0];
    const float* pos        = (const float*)d_in[1];
    const float* x_skip     = (const float*)d_in[3];
    const float* pos_skip   = (const float*)d_in[4];
    const int*   batch_skip = (const int*)d_in[5];
    const float* W1         = (const float*)d_in[6];
    const float* b1         = (const float*)d_in[7];
    const float* W2         = (const float*)d_in[8];
    const float* b2         = (const float*)d_in[9];
    float* out = (float*)d_out;

    __half *Xhi, *Xlo, *Shi, *Slo, *H1hi, *H1lo;
    __half *W1aThi, *W1aTlo, *W1bThi, *W1bTlo, *W2Thi, *W2Tlo;
    float* Z;
    cudaGetSymbolAddress((void**)&Xhi, g_Xhi);
    cudaGetSymbolAddress((void**)&Xlo, g_Xlo);
    cudaGetSymbolAddress((void**)&Shi, g_Shi);
    cudaGetSymbolAddress((void**)&Slo, g_Slo);
    cudaGetSymbolAddress((void**)&H1hi, g_H1hi);
    cudaGetSymbolAddress((void**)&H1lo, g_H1lo);
    cudaGetSymbolAddress((void**)&W1aThi, g_W1aThi);
    cudaGetSymbolAddress((void**)&W1aTlo, g_W1aTlo);
    cudaGetSymbolAddress((void**)&W1bThi, g_W1bThi);
    cudaGetSymbolAddress((void**)&W1bTlo, g_W1bTlo);
    cudaGetSymbolAddress((void**)&W2Thi, g_W2Thi);
    cudaGetSymbolAddress((void**)&W2Tlo, g_W2Tlo);
    cudaGetSymbolAddress((void**)&Z, g_Z);

    cudaFuncSetAttribute(gemm_mma<0>, cudaFuncAttributeMaxDynamicSharedMemorySize, GEMM_SMEM);
    cudaFuncSetAttribute(gemm_mma<1>, cudaFuncAttributeMaxDynamicSharedMemorySize, GEMM_SMEM);
    cudaFuncSetAttribute(gemm_mma<2>, cudaFuncAttributeMaxDynamicSharedMemorySize, GEMM_SMEM);

    // 1) KNN + input splits + weight prep
    knn_kernel<<<MM / 256, 256>>>(pos, pos_skip);
    split_kernel<<<MC * 256 / 4 / 256, 256>>>(x, Xhi, Xlo);
    split_kernel<<<MM * 256 / 4 / 256, 256>>>(x_skip, Shi, Slo);
    transpose_split<<<dim3(512 / 32, 256 / 32), dim3(32, 8)>>>(W1, 512, 256, W1aThi, W1aTlo);
    transpose_split<<<dim3(512 / 32, 256 / 32), dim3(32, 8)>>>(W1 + 256 * 512, 512, 256, W1bThi, W1bTlo);
    transpose_split<<<dim3(256 / 32, 512 / 32), dim3(32, 8)>>>(W2, 256, 512, W2Thi, W2Tlo);

    // 2) Z = x @ W1a            [16384 x 512], K=256
    gemm_mma<0><<<dim3(512 / 128, MC / 128), 256, GEMM_SMEM>>>(
        Xhi, Xlo, W1aThi, W1aTlo, nullptr, nullptr, Z, nullptr, nullptr, 256, 512);

    // 3) H1 = relu(x_skip @ W1b + gather(Z) + b1)  [65536 x 512], K=256
    gemm_mma<1><<<dim3(512 / 128, MM / 128), 256, GEMM_SMEM>>>(
        Shi, Slo, W1bThi, W1bTlo, b1, Z, nullptr, H1hi, H1lo, 256, 512);

    // 4) out = relu(H1 @ W2 + b2)                  [65536 x 256], K=512
    gemm_mma<2><<<dim3(256 / 128, MM / 128), 256, GEMM_SMEM>>>(
        H1hi, H1lo, W2Thi, W2Tlo, b2, nullptr, out, nullptr, nullptr, 512, 256);

    // 5) tail outputs
    const long long FULL = (long long)MM * CC + (long long)MM * 3 + MM;
    if ((long long)out_size >= FULL) {
        tail_kernel<<<(MM * 3 + 255) / 256, 256>>>(pos_skip, batch_skip, out);
    }
}

// round 5
// speedup vs baseline: 2.0059x; 1.0383x over previous
#include <cuda_runtime.h>
#include <cuda_fp16.h>
#include <math.h>
#include <stdint.h>

// ---------------------------------------------------------------- constants
#define BB   16
#define NC   1024
#define NF   4096
#define CC   256
#define MM   (BB * NF)      // 65536 fine points
#define MC   (BB * NC)      // 16384 coarse points

// ---------------------------------------------------------------- scratch
__device__ __align__(16) __half g_Xhi[MC * 256];       // x split
__device__ __align__(16) __half g_Xlo[MC * 256];
__device__ __align__(16) __half g_Shi[MM * 256];       // x_skip split
__device__ __align__(16) __half g_Slo[MM * 256];
__device__ __align__(16) __half g_H1hi[MM * 512];      // layer1 out split
__device__ __align__(16) __half g_H1lo[MM * 512];
__device__ __align__(16) float  g_Z[MC * 512];         // x @ W1a (fp32)
__device__ __align__(16) __half g_W1aThi[512 * 256];   // [N=512][K=256]
__device__ __align__(16) __half g_W1aTlo[512 * 256];
__device__ __align__(16) __half g_W1bThi[512 * 256];
__device__ __align__(16) __half g_W1bTlo[512 * 256];
__device__ __align__(16) __half g_W2Thi[256 * 512];    // [N=256][K=512]
__device__ __align__(16) __half g_W2Tlo[256 * 512];
__device__ int   g_idx[MM * 3];
__device__ float g_w[MM * 3];

// ---------------------------------------------------------------- helpers
__device__ __forceinline__ uint32_t smem_u32(const void* p) {
    uint32_t a;
    asm("{ .reg .u64 t; cvta.to.shared.u64 t, %1; cvt.u32.u64 %0, t; }"
        : "=r"(a) : "l"(p));
    return a;
}
__device__ __forceinline__ void cp16(uint32_t dst, const void* src) {
    asm volatile("cp.async.cg.shared.global [%0], [%1], 16;" :: "r"(dst), "l"(src));
}
__device__ __forceinline__ void ldsm4(uint32_t* r, uint32_t addr) {
    asm volatile("ldmatrix.sync.aligned.m8n8.x4.shared.b16 {%0,%1,%2,%3}, [%4];"
        : "=r"(r[0]), "=r"(r[1]), "=r"(r[2]), "=r"(r[3]) : "r"(addr));
}
__device__ __forceinline__ void mma16816(float* d, const uint32_t* a, const uint32_t* b) {
    asm volatile("mma.sync.aligned.m16n8k16.row.col.f32.f16.f16.f32 "
        "{%0,%1,%2,%3}, {%4,%5,%6,%7}, {%8,%9}, {%0,%1,%2,%3};"
        : "+f"(d[0]), "+f"(d[1]), "+f"(d[2]), "+f"(d[3])
        : "r"(a[0]), "r"(a[1]), "r"(a[2]), "r"(a[3]), "r"(b[0]), "r"(b[1]));
}
__device__ __forceinline__ void split_h(float v, __half& h, __half& l) {
    h = __float2half_rn(v);
    l = __float2half_rn(v - __half2float(h));
}

// ---------------------------------------------------------------- KNN
__global__ void knn_kernel(const float* __restrict__ pos_c,
                           const float* __restrict__ pos_f) {
    __shared__ float4 sp[NC];
    int i = blockIdx.x * 256 + threadIdx.x;
    int b = i >> 12;
    const float* pc = pos_c + (size_t)b * NC * 3;
    for (int t = threadIdx.x; t < NC; t += 256)
        sp[t] = make_float4(pc[t * 3 + 0], pc[t * 3 + 1], pc[t * 3 + 2], 0.0f);
    __syncthreads();

    float px = pos_f[i * 3 + 0], py = pos_f[i * 3 + 1], pz = pos_f[i * 3 + 2];
    float d0 = INFINITY, d1 = INFINITY, d2 = INFINITY;
    int   i0 = 0, i1 = 0, i2 = 0;
    #pragma unroll 4
    for (int j = 0; j < NC; j++) {
        float4 p = sp[j];
        float dx = px - p.x, dy = py - p.y, dz = pz - p.z;
        float d = dx * dx + dy * dy + dz * dz;
        if (d < d2) {
            if (d < d1) {
                if (d < d0) { d2 = d1; i2 = i1; d1 = d0; i1 = i0; d0 = d; i0 = j; }
                else        { d2 = d1; i2 = i1; d1 = d;  i1 = j; }
            } else          { d2 = d;  i2 = j; }
        }
    }
    float w0 = 1.0f / (d0 + 1e-16f), w1 = 1.0f / (d1 + 1e-16f), w2 = 1.0f / (d2 + 1e-16f);
    float inv = 1.0f / (w0 + w1 + w2);
    int base = b * NC;
    g_idx[i * 3 + 0] = base + i0;  g_idx[i * 3 + 1] = base + i1;  g_idx[i * 3 + 2] = base + i2;
    g_w[i * 3 + 0] = w0 * inv;     g_w[i * 3 + 1] = w1 * inv;     g_w[i * 3 + 2] = w2 * inv;
}

// ---------------------------------------------------------------- fp32 -> fp16 hi/lo split
__global__ void split_kernel(const float* __restrict__ in,
                             __half* __restrict__ hi, __half* __restrict__ lo) {
    int t = blockIdx.x * 256 + threadIdx.x;        // float4 index
    float4 v = ((const float4*)in)[t];
    __half h[4], l[4];
    split_h(v.x, h[0], l[0]);  split_h(v.y, h[1], l[1]);
    split_h(v.z, h[2], l[2]);  split_h(v.w, h[3], l[3]);
    ((uint2*)hi)[t] = *(uint2*)h;
    ((uint2*)lo)[t] = *(uint2*)l;
}

// ---------------------------------------------------------------- weight transpose + split
__global__ void transpose_split(const float* __restrict__ in, int N, int Kt,
                                __half* __restrict__ oh, __half* __restrict__ ol) {
    __shared__ float t[32][33];
    int n0 = blockIdx.x * 32, k0 = blockIdx.y * 32;
    int xx = threadIdx.x;
    for (int j = threadIdx.y; j < 32; j += 8)
        t[j][xx] = in[(size_t)(k0 + j) * N + n0 + xx];
    __syncthreads();
    for (int j = threadIdx.y; j < 32; j += 8) {
        __half h, l;
        split_h(t[xx][j], h, l);
        size_t o = (size_t)(n0 + j) * Kt + k0 + xx;
        oh[o] = h;  ol[o] = l;
    }
}

// ---------------------------------------------------------------- mma.sync GEMM
// CTA tile 128x256, warp tile 64x64 (8 warps: 2M x 4N), BK=32, 2-stage cp.async.
// C = (Ahi+Alo)[M,K] @ (Bhi+Blo)^T[N,K]  via hi*hi + hi*lo + lo*hi.
// MODE 0: C -> fp32                       [Z = x @ W1a]
// MODE 1: relu(C + bias + Sum w_k Z[idx_k]) -> fp16 hi/lo   [layer 1]
// MODE 2: relu(C + bias) -> fp32          [layer 2 -> d_out]
#define A_TILE_B  10240               // 128 rows * 80B (32 fp16 padded to 40)
#define B_TILE_B  20480               // 256 rows * 80B
#define OFF_AHI   0
#define OFF_ALO   A_TILE_B
#define OFF_BHI   (2 * A_TILE_B)
#define OFF_BLO   (2 * A_TILE_B + B_TILE_B)
#define STG_B     (2 * A_TILE_B + 2 * B_TILE_B)   // 61440
#define NSTG      2
#define GEMM_SMEM (NSTG * STG_B)                  // 122880

template<int MODE>
__global__ __launch_bounds__(256, 1)
void gemm_mma(const __half* __restrict__ Ahi, const __half* __restrict__ Alo,
              const __half* __restrict__ Bhi, const __half* __restrict__ Blo,
              const float* __restrict__ bias, const float* __restrict__ Zt,
              float* __restrict__ outF,
              __half* __restrict__ outHi, __half* __restrict__ outLo,
              int K, int ldout) {
    extern __shared__ __align__(128) char smem[];
    const uint32_t sbase = smem_u32(smem);
    const int tid  = threadIdx.x;
    const int wid  = tid >> 5, lane = tid & 31;
    const int wm   = (wid >> 2) * 64;          // warp M offset (0/64)
    const int wn   = (wid & 3) * 64;           // warp N offset (0..192)
    const int bm   = blockIdx.y * 128, bn = blockIdx.x * 256;
    const int KT   = K >> 5;                   // BK=32 tiles

    // cp.async decomposition: rows of 32 fp16 = 64B = 4 chunks of 16B
    const int rA = tid >> 2, qA = tid & 3;     // A: 512 segs, 2 loops
    const int rB = tid >> 2, qB = tid & 3;     // B: 1024 segs, 4 loops

    auto load_tile = [&](int kt, int stg) {
        const uint32_t sb = sbase + stg * STG_B;
        const size_t ka = (size_t)kt * 32;
        #pragma unroll
        for (int l = 0; l < 2; l++) {          // A hi/lo: 128 rows
            int r = rA + l * 64;
            size_t ar = (size_t)(bm + r) * K + ka + qA * 8;
            uint32_t d = r * 80 + qA * 16;
            cp16(sb + OFF_AHI + d, Ahi + ar);
            cp16(sb + OFF_ALO + d, Alo + ar);
        }
        #pragma unroll
        for (int l = 0; l < 4; l++) {          // B hi/lo: 256 rows
            int r = rB + l * 64;
            size_t br = (size_t)(bn + r) * K + ka + qB * 8;
            uint32_t d = r * 80 + qB * 16;
            cp16(sb + OFF_BHI + d, Bhi + br);
            cp16(sb + OFF_BLO + d, Blo + br);
        }
        asm volatile("cp.async.commit_group;" ::: "memory");
    };

    float acc[4][8][4];
    #pragma unroll
    for (int a = 0; a < 4; a++)
        #pragma unroll
        for (int b = 0; b < 8; b++)
            #pragma unroll
            for (int c = 0; c < 4; c++) acc[a][b][c] = 0.0f;

    const int lmr = (lane & 7) + ((lane >> 3) & 1) * 8;   // row within 16-row tile
    const int lmc = (lane >> 4) & 1;                       // k8 half

    load_tile(0, 0);

    for (int kt = 0; kt < KT; kt++) {
        asm volatile("cp.async.wait_group 0;" ::: "memory");
        __syncthreads();
        if (kt + 1 < KT) load_tile(kt + 1, (kt + 1) & 1);

        const uint32_t sb   = sbase + (kt & 1) * STG_B;
        const uint32_t aOff = sb + OFF_AHI + (wm + lmr) * 80 + lmc * 16;
        const uint32_t bOff = sb + OFF_BHI + (wn + lmr) * 80 + lmc * 16;

        #pragma unroll
        for (int kc = 0; kc < 2; kc++) {
            uint32_t aH[4][4], aL[4][4];
            #pragma unroll
            for (int mt = 0; mt < 4; mt++) {
                ldsm4(aH[mt], aOff + mt * 16 * 80 + kc * 32);
                ldsm4(aL[mt], aOff + (OFF_ALO - OFF_AHI) + mt * 16 * 80 + kc * 32);
            }
            // two 32-col halves of the 64-wide warp N tile
            #pragma unroll
            for (int nh = 0; nh < 2; nh++) {
                uint32_t bH[4][2], bL[4][2];
                #pragma unroll
                for (int bt = 0; bt < 2; bt++) {
                    uint32_t t4[4];
                    uint32_t bo = bOff + (nh * 2 + bt) * 16 * 80 + kc * 32;
                    ldsm4(t4, bo);
                    bH[bt * 2][0] = t4[0];     bH[bt * 2][1] = t4[2];
                    bH[bt * 2 + 1][0] = t4[1]; bH[bt * 2 + 1][1] = t4[3];
                    ldsm4(t4, bo + (OFF_BLO - OFF_BHI));
                    bL[bt * 2][0] = t4[0];     bL[bt * 2][1] = t4[2];
                    bL[bt * 2 + 1][0] = t4[1]; bL[bt * 2 + 1][1] = t4[3];
                }
                #pragma unroll
                for (int mt = 0; mt < 4; mt++)
                    #pragma unroll
                    for (int nt = 0; nt < 4; nt++)
                        mma16816(acc[mt][nh * 4 + nt], aH[mt], bH[nt]);
                #pragma unroll
                for (int mt = 0; mt < 4; mt++)
                    #pragma unroll
                    for (int nt = 0; nt < 4; nt++)
                        mma16816(acc[mt][nh * 4 + nt], aH[mt], bL[nt]);
                #pragma unroll
                for (int mt = 0; mt < 4; mt++)
                    #pragma unroll
                    for (int nt = 0; nt < 4; nt++)
                        mma16816(acc[mt][nh * 4 + nt], aL[mt], bH[nt]);
            }
        }
    }

    // ---------------- epilogue ----------------
    #pragma unroll
    for (int mt = 0; mt < 4; mt++) {
        int r0 = bm + wm + mt * 16 + (lane >> 2);
        int r1 = r0 + 8;
        int   ja0 = 0, ja1 = 0, ja2 = 0, jb0 = 0, jb1 = 0, jb2 = 0;
        float wa0 = 0, wa1 = 0, wa2 = 0, wb0 = 0, wb1 = 0, wb2 = 0;
        if (MODE == 1) {
            ja0 = g_idx[r0 * 3 + 0]; ja1 = g_idx[r0 * 3 + 1]; ja2 = g_idx[r0 * 3 + 2];
            wa0 = g_w[r0 * 3 + 0];   wa1 = g_w[r0 * 3 + 1];   wa2 = g_w[r0 * 3 + 2];
            jb0 = g_idx[r1 * 3 + 0]; jb1 = g_idx[r1 * 3 + 1]; jb2 = g_idx[r1 * 3 + 2];
            wb0 = g_w[r1 * 3 + 0];   wb1 = g_w[r1 * 3 + 1];   wb2 = g_w[r1 * 3 + 2];
        }
        #pragma unroll
        for (int nt = 0; nt < 8; nt++) {
            int c = bn + wn + nt * 8 + (lane & 3) * 2;
            float v0 = acc[mt][nt][0], v1 = acc[mt][nt][1];
            float v2 = acc[mt][nt][2], v3 = acc[mt][nt][3];
            if (MODE != 0) {
                float2 bv = *(const float2*)(bias + c);
                v0 += bv.x; v1 += bv.y; v2 += bv.x; v3 += bv.y;
            }
            if (MODE == 1) {
                float2 z;
                z = *(const float2*)(Zt + (size_t)ja0 * 512 + c); v0 += wa0 * z.x; v1 += wa0 * z.y;
                z = *(const float2*)(Zt + (size_t)ja1 * 512 + c); v0 += wa1 * z.x; v1 += wa1 * z.y;
                z = *(const float2*)(Zt + (size_t)ja2 * 512 + c); v0 += wa2 * z.x; v1 += wa2 * z.y;
                z = *(const float2*)(Zt + (size_t)jb0 * 512 + c); v2 += wb0 * z.x; v3 += wb0 * z.y;
                z = *(const float2*)(Zt + (size_t)jb1 * 512 + c); v2 += wb1 * z.x; v3 += wb1 * z.y;
                z = *(const float2*)(Zt + (size_t)jb2 * 512 + c); v2 += wb2 * z.x; v3 += wb2 * z.y;
            }
            if (MODE != 0) {
                v0 = fmaxf(v0, 0.0f); v1 = fmaxf(v1, 0.0f);
                v2 = fmaxf(v2, 0.0f); v3 = fmaxf(v3, 0.0f);
            }
            if (MODE == 1) {
                __half h0, l0, h1, l1;
                split_h(v0, h0, l0); split_h(v1, h1, l1);
                *(__half2*)(outHi + (size_t)r0 * ldout + c) = __halves2half2(h0, h1);
                *(__half2*)(outLo + (size_t)r0 * ldout + c) = __halves2half2(l0, l1);
                split_h(v2, h0, l0); split_h(v3, h1, l1);
                *(__half2*)(outHi + (size_t)r1 * ldout + c) = __halves2half2(h0, h1);
                *(__half2*)(outLo + (size_t)r1 * ldout + c) = __halves2half2(l0, l1);
            } else {
                *(float2*)(outF + (size_t)r0 * ldout + c) = make_float2(v0, v1);
                *(float2*)(outF + (size_t)r1 * ldout + c) = make_float2(v2, v3);
            }
        }
    }
}

// ---------------------------------------------------------------- tail
__global__ void tail_kernel(const float* __restrict__ pos_skip,
                            const int* __restrict__ batch_skip,
                            float* __restrict__ out) {
    int t = blockIdx.x * 256 + threadIdx.x;
    const size_t POS_OFF = (size_t)MM * CC;
    const size_t BAT_OFF = POS_OFF + (size_t)MM * 3;
    if (t < MM * 3) out[POS_OFF + t] = pos_skip[t];
    if (t < MM)     out[BAT_OFF + t] = (float)batch_skip[t];
}

// ---------------------------------------------------------------- launch
extern "C" void kernel_launch(void* const* d_in, const int* in_sizes, int n_in,
                              void* d_out, int out_size) {
    const float* x          = (const float*)d_in[0];
    const float* pos        = (const float*)d_in[1];
    const float* x_skip     = (const float*)d_in[3];
    const float* pos_skip   = (const float*)d_in[4];
    const int*   batch_skip = (const int*)d_in[5];
    const float* W1         = (const float*)d_in[6];
    const float* b1         = (const float*)d_in[7];
    const float* W2         = (const float*)d_in[8];
    const float* b2         = (const float*)d_in[9];
    float* out = (float*)d_out;

    __half *Xhi, *Xlo, *Shi, *Slo, *H1hi, *H1lo;
    __half *W1aThi, *W1aTlo, *W1bThi, *W1bTlo, *W2Thi, *W2Tlo;
    float* Z;
    cudaGetSymbolAddress((void**)&Xhi, g_Xhi);
    cudaGetSymbolAddress((void**)&Xlo, g_Xlo);
    cudaGetSymbolAddress((void**)&Shi, g_Shi);
    cudaGetSymbolAddress((void**)&Slo, g_Slo);
    cudaGetSymbolAddress((void**)&H1hi, g_H1hi);
    cudaGetSymbolAddress((void**)&H1lo, g_H1lo);
    cudaGetSymbolAddress((void**)&W1aThi, g_W1aThi);
    cudaGetSymbolAddress((void**)&W1aTlo, g_W1aTlo);
    cudaGetSymbolAddress((void**)&W1bThi, g_W1bThi);
    cudaGetSymbolAddress((void**)&W1bTlo, g_W1bTlo);
    cudaGetSymbolAddress((void**)&W2Thi, g_W2Thi);
    cudaGetSymbolAddress((void**)&W2Tlo, g_W2Tlo);
    cudaGetSymbolAddress((void**)&Z, g_Z);

    cudaFuncSetAttribute(gemm_mma<0>, cudaFuncAttributeMaxDynamicSharedMemorySize, GEMM_SMEM);
    cudaFuncSetAttribute(gemm_mma<1>, cudaFuncAttributeMaxDynamicSharedMemorySize, GEMM_SMEM);
    cudaFuncSetAttribute(gemm_mma<2>, cudaFuncAttributeMaxDynamicSharedMemorySize, GEMM_SMEM);

    // 1) KNN + input splits + weight prep
    knn_kernel<<<MM / 256, 256>>>(pos, pos_skip);
    split_kernel<<<MC * 256 / 4 / 256, 256>>>(x, Xhi, Xlo);
    split_kernel<<<MM * 256 / 4 / 256, 256>>>(x_skip, Shi, Slo);
    transpose_split<<<dim3(512 / 32, 256 / 32), dim3(32, 8)>>>(W1, 512, 256, W1aThi, W1aTlo);
    transpose_split<<<dim3(512 / 32, 256 / 32), dim3(32, 8)>>>(W1 + 256 * 512, 512, 256, W1bThi, W1bTlo);
    transpose_split<<<dim3(256 / 32, 512 / 32), dim3(32, 8)>>>(W2, 256, 512, W2Thi, W2Tlo);

    // 2) Z = x @ W1a            [16384 x 512], K=256
    gemm_mma<0><<<dim3(512 / 256, MC / 128), 256, GEMM_SMEM>>>(
        Xhi, Xlo, W1aThi, W1aTlo, nullptr, nullptr, Z, nullptr, nullptr, 256, 512);

    // 3) H1 = relu(x_skip @ W1b + gather(Z) + b1)  [65536 x 512], K=256
    gemm_mma<1><<<dim3(512 / 256, MM / 128), 256, GEMM_SMEM>>>(
        Shi, Slo, W1bThi, W1bTlo, b1, Z, nullptr, H1hi, H1lo, 256, 512);

    // 4) out = relu(H1 @ W2 + b2)                  [65536 x 256], K=512
    gemm_mma<2><<<dim3(256 / 256, MM / 128), 256, GEMM_SMEM>>>(
        H1hi, H1lo, W2Thi, W2Tlo, b2, nullptr, out, nullptr, nullptr, 512, 256);

    // 5) tail outputs
    const long long FULL = (long long)MM * CC + (long long)MM * 3 + MM;
    if ((long long)out_size >= FULL) {
        tail_kernel<<<(MM * 3 + 255) / 256, 256>>>(pos_skip, batch_skip, out);
    }
}

// round 6
// speedup vs baseline: 2.6315x; 1.3119x over previous
#include <cuda_runtime.h>
#include <cuda_fp16.h>
#include <math.h>
#include <stdint.h>

// ---------------------------------------------------------------- constants
#define BB   16
#define NC   1024
#define NF   4096
#define CC   256
#define MM   (BB * NF)      // 65536 fine points
#define MC   (BB * NC)      // 16384 coarse points

// ---------------------------------------------------------------- scratch
__device__ __align__(16) __half g_Xh[MC * 256];        // x  (fp16)
__device__ __align__(16) __half g_Sh[MM * 256];        // x_skip (fp16)
__device__ __align__(16) __half g_H1h[MM * 512];       // layer1 out (fp16)
__device__ __align__(16) float  g_Z[MC * 512];         // x @ W1a (fp32)
__device__ __align__(16) __half g_W1aThi[512 * 256];   // [N=512][K=256] hi
__device__ __align__(16) __half g_W1aTlo[512 * 256];
__device__ __align__(16) __half g_W1bThi[512 * 256];
__device__ __align__(16) __half g_W1bTlo[512 * 256];
__device__ __align__(16) __half g_W2Thi[256 * 512];    // [N=256][K=512]
__device__ __align__(16) __half g_W2Tlo[256 * 512];
__device__ int   g_idx[MM * 3];
__device__ float g_w[MM * 3];

// ---------------------------------------------------------------- helpers
__device__ __forceinline__ uint32_t smem_u32(const void* p) {
    uint32_t a;
    asm("{ .reg .u64 t; cvta.to.shared.u64 t, %1; cvt.u32.u64 %0, t; }"
        : "=r"(a) : "l"(p));
    return a;
}
__device__ __forceinline__ void cp16(uint32_t dst, const void* src) {
    asm volatile("cp.async.cg.shared.global [%0], [%1], 16;" :: "r"(dst), "l"(src));
}
__device__ __forceinline__ void ldsm4(uint32_t* r, uint32_t addr) {
    asm volatile("ldmatrix.sync.aligned.m8n8.x4.shared.b16 {%0,%1,%2,%3}, [%4];"
        : "=r"(r[0]), "=r"(r[1]), "=r"(r[2]), "=r"(r[3]) : "r"(addr));
}
__device__ __forceinline__ void mma16816(float* d, const uint32_t* a, const uint32_t* b) {
    asm volatile("mma.sync.aligned.m16n8k16.row.col.f32.f16.f16.f32 "
        "{%0,%1,%2,%3}, {%4,%5,%6,%7}, {%8,%9}, {%0,%1,%2,%3};"
        : "+f"(d[0]), "+f"(d[1]), "+f"(d[2]), "+f"(d[3])
        : "r"(a[0]), "r"(a[1]), "r"(a[2]), "r"(a[3]), "r"(b[0]), "r"(b[1]));
}
__device__ __forceinline__ void split_h(float v, __half& h, __half& l) {
    h = __float2half_rn(v);
    l = __float2half_rn(v - __half2float(h));
}

// ---------------------------------------------------------------- KNN
__global__ void knn_kernel(const float* __restrict__ pos_c,
                           const float* __restrict__ pos_f) {
    __shared__ float4 sp[NC];
    int i = blockIdx.x * 256 + threadIdx.x;
    int b = i >> 12;
    const float* pc = pos_c + (size_t)b * NC * 3;
    for (int t = threadIdx.x; t < NC; t += 256)
        sp[t] = make_float4(pc[t * 3 + 0], pc[t * 3 + 1], pc[t * 3 + 2], 0.0f);
    __syncthreads();

    float px = pos_f[i * 3 + 0], py = pos_f[i * 3 + 1], pz = pos_f[i * 3 + 2];
    float d0 = INFINITY, d1 = INFINITY, d2 = INFINITY;
    int   i0 = 0, i1 = 0, i2 = 0;
    #pragma unroll 4
    for (int j = 0; j < NC; j++) {
        float4 p = sp[j];
        float dx = px - p.x, dy = py - p.y, dz = pz - p.z;
        float d = dx * dx + dy * dy + dz * dz;
        if (d < d2) {
            if (d < d1) {
                if (d < d0) { d2 = d1; i2 = i1; d1 = d0; i1 = i0; d0 = d; i0 = j; }
                else        { d2 = d1; i2 = i1; d1 = d;  i1 = j; }
            } else          { d2 = d;  i2 = j; }
        }
    }
    float w0 = 1.0f / (d0 + 1e-16f), w1 = 1.0f / (d1 + 1e-16f), w2 = 1.0f / (d2 + 1e-16f);
    float inv = 1.0f / (w0 + w1 + w2);
    int base = b * NC;
    g_idx[i * 3 + 0] = base + i0;  g_idx[i * 3 + 1] = base + i1;  g_idx[i * 3 + 2] = base + i2;
    g_w[i * 3 + 0] = w0 * inv;     g_w[i * 3 + 1] = w1 * inv;     g_w[i * 3 + 2] = w2 * inv;
}

// ---------------------------------------------------------------- fp32 -> fp16 convert
__global__ void tofp16_kernel(const float* __restrict__ in, __half* __restrict__ out) {
    int t = blockIdx.x * 256 + threadIdx.x;        // float4 index
    float4 v = ((const float4*)in)[t];
    __half h[4];
    h[0] = __float2half_rn(v.x);  h[1] = __float2half_rn(v.y);
    h[2] = __float2half_rn(v.z);  h[3] = __float2half_rn(v.w);
    ((uint2*)out)[t] = *(uint2*)h;
}

// ---------------------------------------------------------------- weight transpose + split
__global__ void transpose_split(const float* __restrict__ in, int N, int Kt,
                                __half* __restrict__ oh, __half* __restrict__ ol) {
    __shared__ float t[32][33];
    int n0 = blockIdx.x * 32, k0 = blockIdx.y * 32;
    int xx = threadIdx.x;
    for (int j = threadIdx.y; j < 32; j += 8)
        t[j][xx] = in[(size_t)(k0 + j) * N + n0 + xx];
    __syncthreads();
    for (int j = threadIdx.y; j < 32; j += 8) {
        __half h, l;
        split_h(t[xx][j], h, l);
        size_t o = (size_t)(n0 + j) * Kt + k0 + xx;
        oh[o] = h;  ol[o] = l;
    }
}

// ---------------------------------------------------------------- mma.sync GEMM
// CTA tile 128x256, warp tile 64x64 (8 warps: 2M x 4N), BK=32, 2-stage cp.async.
// C = A_fp16[M,K] @ (Bhi+Blo)^T[N,K]   (2-term weight split)
// MODE 0: C -> fp32                       [Z = x @ W1a]
// MODE 1: relu(C + bias + Sum w_k Z[idx_k]) -> fp16   [layer 1]
// MODE 2: relu(C + bias) -> fp32          [layer 2 -> d_out]
#define A_TILE_B  10240               // 128 rows * 80B (32 fp16 padded to 40)
#define B_TILE_B  20480               // 256 rows * 80B
#define OFF_A     0
#define OFF_BHI   A_TILE_B
#define OFF_BLO   (A_TILE_B + B_TILE_B)
#define STG_B     (A_TILE_B + 2 * B_TILE_B)       // 51200
#define NSTG      2
#define GEMM_SMEM (NSTG * STG_B)                  // 102400

template<int MODE>
__global__ __launch_bounds__(256, 1)
void gemm_mma(const __half* __restrict__ A,
              const __half* __restrict__ Bhi, const __half* __restrict__ Blo,
              const float* __restrict__ bias, const float* __restrict__ Zt,
              float* __restrict__ outF, __half* __restrict__ outH,
              int K, int ldout) {
    extern __shared__ __align__(128) char smem[];
    const uint32_t sbase = smem_u32(smem);
    const int tid  = threadIdx.x;
    const int wid  = tid >> 5, lane = tid & 31;
    const int wm   = (wid >> 2) * 64;          // warp M offset (0/64)
    const int wn   = (wid & 3) * 64;           // warp N offset (0..192)
    const int bm   = blockIdx.y * 128, bn = blockIdx.x * 256;
    const int KT   = K >> 5;                   // BK=32 tiles

    const int rA = tid >> 2, qA = tid & 3;     // 16B chunk decomposition

    auto load_tile = [&](int kt, int stg) {
        const uint32_t sb = sbase + stg * STG_B;
        const size_t ka = (size_t)kt * 32;
        #pragma unroll
        for (int l = 0; l < 2; l++) {          // A: 128 rows x 4 chunks
            int r = rA + l * 64;
            size_t ar = (size_t)(bm + r) * K + ka + qA * 8;
            cp16(sb + OFF_A + r * 80 + qA * 16, A + ar);
        }
        #pragma unroll
        for (int l = 0; l < 4; l++) {          // B hi/lo: 256 rows x 4 chunks
            int r = rA + l * 64;
            size_t br = (size_t)(bn + r) * K + ka + qA * 8;
            uint32_t d = r * 80 + qA * 16;
            cp16(sb + OFF_BHI + d, Bhi + br);
            cp16(sb + OFF_BLO + d, Blo + br);
        }
        asm volatile("cp.async.commit_group;" ::: "memory");
    };

    float acc[4][8][4];
    #pragma unroll
    for (int a = 0; a < 4; a++)
        #pragma unroll
        for (int b = 0; b < 8; b++)
            #pragma unroll
            for (int c = 0; c < 4; c++) acc[a][b][c] = 0.0f;

    const int lmr = (lane & 7) + ((lane >> 3) & 1) * 8;
    const int lmc = (lane >> 4) & 1;

    load_tile(0, 0);

    for (int kt = 0; kt < KT; kt++) {
        asm volatile("cp.async.wait_group 0;" ::: "memory");
        __syncthreads();
        if (kt + 1 < KT) load_tile(kt + 1, (kt + 1) & 1);

        const uint32_t sb   = sbase + (kt & 1) * STG_B;
        const uint32_t aOff = sb + OFF_A   + (wm + lmr) * 80 + lmc * 16;
        const uint32_t bOff = sb + OFF_BHI + (wn + lmr) * 80 + lmc * 16;

        #pragma unroll
        for (int kc = 0; kc < 2; kc++) {
            uint32_t aR[4][4];
            #pragma unroll
            for (int mt = 0; mt < 4; mt++)
                ldsm4(aR[mt], aOff + mt * 16 * 80 + kc * 32);
            #pragma unroll
            for (int nh = 0; nh < 2; nh++) {
                uint32_t bH[4][2], bL[4][2];
                #pragma unroll
                for (int bt = 0; bt < 2; bt++) {
                    uint32_t t4[4];
                    uint32_t bo = bOff + (nh * 2 + bt) * 16 * 80 + kc * 32;
                    ldsm4(t4, bo);
                    bH[bt * 2][0] = t4[0];     bH[bt * 2][1] = t4[2];
                    bH[bt * 2 + 1][0] = t4[1]; bH[bt * 2 + 1][1] = t4[3];
                    ldsm4(t4, bo + (OFF_BLO - OFF_BHI));
                    bL[bt * 2][0] = t4[0];     bL[bt * 2][1] = t4[2];
                    bL[bt * 2 + 1][0] = t4[1]; bL[bt * 2 + 1][1] = t4[3];
                }
                #pragma unroll
                for (int mt = 0; mt < 4; mt++)
                    #pragma unroll
                    for (int nt = 0; nt < 4; nt++)
                        mma16816(acc[mt][nh * 4 + nt], aR[mt], bH[nt]);
                #pragma unroll
                for (int mt = 0; mt < 4; mt++)
                    #pragma unroll
                    for (int nt = 0; nt < 4; nt++)
                        mma16816(acc[mt][nh * 4 + nt], aR[mt], bL[nt]);
            }
        }
    }

    // ---------------- epilogue ----------------
    #pragma unroll
    for (int mt = 0; mt < 4; mt++) {
        int r0 = bm + wm + mt * 16 + (lane >> 2);
        int r1 = r0 + 8;
        int   ja0 = 0, ja1 = 0, ja2 = 0, jb0 = 0, jb1 = 0, jb2 = 0;
        float wa0 = 0, wa1 = 0, wa2 = 0, wb0 = 0, wb1 = 0, wb2 = 0;
        if (MODE == 1) {
            ja0 = g_idx[r0 * 3 + 0]; ja1 = g_idx[r0 * 3 + 1]; ja2 = g_idx[r0 * 3 + 2];
            wa0 = g_w[r0 * 3 + 0];   wa1 = g_w[r0 * 3 + 1];   wa2 = g_w[r0 * 3 + 2];
            jb0 = g_idx[r1 * 3 + 0]; jb1 = g_idx[r1 * 3 + 1]; jb2 = g_idx[r1 * 3 + 2];
            wb0 = g_w[r1 * 3 + 0];   wb1 = g_w[r1 * 3 + 1];   wb2 = g_w[r1 * 3 + 2];
        }
        #pragma unroll
        for (int nt = 0; nt < 8; nt++) {
            int c = bn + wn + nt * 8 + (lane & 3) * 2;
            float v0 = acc[mt][nt][0], v1 = acc[mt][nt][1];
            float v2 = acc[mt][nt][2], v3 = acc[mt][nt][3];
            if (MODE != 0) {
                float2 bv = *(const float2*)(bias + c);
                v0 += bv.x; v1 += bv.y; v2 += bv.x; v3 += bv.y;
            }
            if (MODE == 1) {
                float2 z;
                z = *(const float2*)(Zt + (size_t)ja0 * 512 + c); v0 += wa0 * z.x; v1 += wa0 * z.y;
                z = *(const float2*)(Zt + (size_t)ja1 * 512 + c); v0 += wa1 * z.x; v1 += wa1 * z.y;
                z = *(const float2*)(Zt + (size_t)ja2 * 512 + c); v0 += wa2 * z.x; v1 += wa2 * z.y;
                z = *(const float2*)(Zt + (size_t)jb0 * 512 + c); v2 += wb0 * z.x; v3 += wb0 * z.y;
                z = *(const float2*)(Zt + (size_t)jb1 * 512 + c); v2 += wb1 * z.x; v3 += wb1 * z.y;
                z = *(const float2*)(Zt + (size_t)jb2 * 512 + c); v2 += wb2 * z.x; v3 += wb2 * z.y;
            }
            if (MODE != 0) {
                v0 = fmaxf(v0, 0.0f); v1 = fmaxf(v1, 0.0f);
                v2 = fmaxf(v2, 0.0f); v3 = fmaxf(v3, 0.0f);
            }
            if (MODE == 1) {
                *(__half2*)(outH + (size_t)r0 * ldout + c) =
                    __halves2half2(__float2half_rn(v0), __float2half_rn(v1));
                *(__half2*)(outH + (size_t)r1 * ldout + c) =
                    __halves2half2(__float2half_rn(v2), __float2half_rn(v3));
            } else {
                *(float2*)(outF + (size_t)r0 * ldout + c) = make_float2(v0, v1);
                *(float2*)(outF + (size_t)r1 * ldout + c) = make_float2(v2, v3);
            }
        }
    }
}

// ---------------------------------------------------------------- tail
__global__ void tail_kernel(const float* __restrict__ pos_skip,
                            const int* __restrict__ batch_skip,
                            float* __restrict__ out) {
    int t = blockIdx.x * 256 + threadIdx.x;
    const size_t POS_OFF = (size_t)MM * CC;
    const size_t BAT_OFF = POS_OFF + (size_t)MM * 3;
    if (t < MM * 3) out[POS_OFF + t] = pos_skip[t];
    if (t < MM)     out[BAT_OFF + t] = (float)batch_skip[t];
}

// ---------------------------------------------------------------- launch
extern "C" void kernel_launch(void* const* d_in, const int* in_sizes, int n_in,
                              void* d_out, int out_size) {
    const float* x          = (const float*)d_in[0];
    const float* pos        = (const float*)d_in[1];
    const float* x_skip     = (const float*)d_in[3];
    const float* pos_skip   = (const float*)d_in[4];
    const int*   batch_skip = (const int*)d_in[5];
    const float* W1         = (const float*)d_in[6];
    const float* b1         = (const float*)d_in[7];
    const float* W2         = (const float*)d_in[8];
    const float* b2         = (const float*)d_in[9];
    float* out = (float*)d_out;

    __half *Xh, *Sh, *H1h;
    __half *W1aThi, *W1aTlo, *W1bThi, *W1bTlo, *W2Thi, *W2Tlo;
    float* Z;
    cudaGetSymbolAddress((void**)&Xh, g_Xh);
    cudaGetSymbolAddress((void**)&Sh, g_Sh);
    cudaGetSymbolAddress((void**)&H1h, g_H1h);
    cudaGetSymbolAddress((void**)&W1aThi, g_W1aThi);
    cudaGetSymbolAddress((void**)&W1aTlo, g_W1aTlo);
    cudaGetSymbolAddress((void**)&W1bThi, g_W1bThi);
    cudaGetSymbolAddress((void**)&W1bTlo, g_W1bTlo);
    cudaGetSymbolAddress((void**)&W2Thi, g_W2Thi);
    cudaGetSymbolAddress((void**)&W2Tlo, g_W2Tlo);
    cudaGetSymbolAddress((void**)&Z, g_Z);

    cudaFuncSetAttribute(gemm_mma<0>, cudaFuncAttributeMaxDynamicSharedMemorySize, GEMM_SMEM);
    cudaFuncSetAttribute(gemm_mma<1>, cudaFuncAttributeMaxDynamicSharedMemorySize, GEMM_SMEM);
    cudaFuncSetAttribute(gemm_mma<2>, cudaFuncAttributeMaxDynamicSharedMemorySize, GEMM_SMEM);

    // 1) KNN + input converts + weight prep
    knn_kernel<<<MM / 256, 256>>>(pos, pos_skip);
    tofp16_kernel<<<MC * 256 / 4 / 256, 256>>>(x, Xh);
    tofp16_kernel<<<MM * 256 / 4 / 256, 256>>>(x_skip, Sh);
    transpose_split<<<dim3(512 / 32, 256 / 32), dim3(32, 8)>>>(W1, 512, 256, W1aThi, W1aTlo);
    transpose_split<<<dim3(512 / 32, 256 / 32), dim3(32, 8)>>>(W1 + 256 * 512, 512, 256, W1bThi, W1bTlo);
    transpose_split<<<dim3(256 / 32, 512 / 32), dim3(32, 8)>>>(W2, 256, 512, W2Thi, W2Tlo);

    // 2) Z = x @ W1a            [16384 x 512], K=256
    gemm_mma<0><<<dim3(512 / 256, MC / 128), 256, GEMM_SMEM>>>(
        Xh, W1aThi, W1aTlo, nullptr, nullptr, Z, nullptr, 256, 512);

    // 3) H1 = relu(x_skip @ W1b + gather(Z) + b1)  [65536 x 512], K=256
    gemm_mma<1><<<dim3(512 / 256, MM / 128), 256, GEMM_SMEM>>>(
        Sh, W1bThi, W1bTlo, b1, Z, nullptr, H1h, 256, 512);

    // 4) out = relu(H1 @ W2 + b2)                  [65536 x 256], K=512
    gemm_mma<2><<<dim3(256 / 256, MM / 128), 256, GEMM_SMEM>>>(
        H1h, W2Thi, W2Tlo, b2, nullptr, out, nullptr, 512, 256);

    // 5) tail outputs
    const long long FULL = (long long)MM * CC + (long long)MM * 3 + MM;
    if ((long long)out_size >= FULL) {
        tail_kernel<<<(MM * 3 + 255) / 256, 256>>>(pos_skip, batch_skip, out);
    }
}

// round 7
// speedup vs baseline: 3.5861x; 1.3628x over previous
#include <cuda_runtime.h>
#include <cuda_fp16.h>
#include <math.h>
#include <stdint.h>

// ---------------------------------------------------------------- constants
#define BB   16
#define NC   1024
#define NF   4096
#define CC   256
#define MM   (BB * NF)      // 65536 fine points
#define MC   (BB * NC)      // 16384 coarse points

// ---------------------------------------------------------------- scratch
__device__ __align__(16) __half g_Xh[MC * 256];        // x  (fp16)
__device__ __align__(16) __half g_Sh[MM * 256];        // x_skip (fp16)
__device__ __align__(16) __half g_H1h[MM * 512];       // layer1 out (fp16)
__device__ __align__(16) float  g_Z[MC * 512];         // x @ W1a (fp32)
__device__ __align__(16) __half g_W1aT[512 * 256];     // [N=512][K=256]
__device__ __align__(16) __half g_W1bT[512 * 256];
__device__ __align__(16) __half g_W2T[256 * 512];      // [N=256][K=512]
__device__ int   g_idx[MM * 3];
__device__ float g_w[MM * 3];

// ---------------------------------------------------------------- helpers
__device__ __forceinline__ uint32_t smem_u32(const void* p) {
    uint32_t a;
    asm("{ .reg .u64 t; cvta.to.shared.u64 t, %1; cvt.u32.u64 %0, t; }"
        : "=r"(a) : "l"(p));
    return a;
}
__device__ __forceinline__ void cp16(uint32_t dst, const void* src) {
    asm volatile("cp.async.cg.shared.global [%0], [%1], 16;" :: "r"(dst), "l"(src));
}
__device__ __forceinline__ void ldsm4(uint32_t* r, uint32_t addr) {
    asm volatile("ldmatrix.sync.aligned.m8n8.x4.shared.b16 {%0,%1,%2,%3}, [%4];"
        : "=r"(r[0]), "=r"(r[1]), "=r"(r[2]), "=r"(r[3]) : "r"(addr));
}
__device__ __forceinline__ void mma16816(float* d, const uint32_t* a, const uint32_t* b) {
    asm volatile("mma.sync.aligned.m16n8k16.row.col.f32.f16.f16.f32 "
        "{%0,%1,%2,%3}, {%4,%5,%6,%7}, {%8,%9}, {%0,%1,%2,%3};"
        : "+f"(d[0]), "+f"(d[1]), "+f"(d[2]), "+f"(d[3])
        : "r"(a[0]), "r"(a[1]), "r"(a[2]), "r"(a[3]), "r"(b[0]), "r"(b[1]));
}

// ---------------------------------------------------------------- KNN
__global__ void knn_kernel(const float* __restrict__ pos_c,
                           const float* __restrict__ pos_f) {
    __shared__ float4 sp[NC];
    int i = blockIdx.x * 256 + threadIdx.x;
    int b = i >> 12;
    const float* pc = pos_c + (size_t)b * NC * 3;
    for (int t = threadIdx.x; t < NC; t += 256)
        sp[t] = make_float4(pc[t * 3 + 0], pc[t * 3 + 1], pc[t * 3 + 2], 0.0f);
    __syncthreads();

    float px = pos_f[i * 3 + 0], py = pos_f[i * 3 + 1], pz = pos_f[i * 3 + 2];
    float d0 = INFINITY, d1 = INFINITY, d2 = INFINITY;
    int   i0 = 0, i1 = 0, i2 = 0;
    #pragma unroll 4
    for (int j = 0; j < NC; j++) {
        float4 p = sp[j];
        float dx = px - p.x, dy = py - p.y, dz = pz - p.z;
        float d = dx * dx + dy * dy + dz * dz;
        if (d < d2) {
            if (d < d1) {
                if (d < d0) { d2 = d1; i2 = i1; d1 = d0; i1 = i0; d0 = d; i0 = j; }
                else        { d2 = d1; i2 = i1; d1 = d;  i1 = j; }
            } else          { d2 = d;  i2 = j; }
        }
    }
    float w0 = 1.0f / (d0 + 1e-16f), w1 = 1.0f / (d1 + 1e-16f), w2 = 1.0f / (d2 + 1e-16f);
    float inv = 1.0f / (w0 + w1 + w2);
    int base = b * NC;
    g_idx[i * 3 + 0] = base + i0;  g_idx[i * 3 + 1] = base + i1;  g_idx[i * 3 + 2] = base + i2;
    g_w[i * 3 + 0] = w0 * inv;     g_w[i * 3 + 1] = w1 * inv;     g_w[i * 3 + 2] = w2 * inv;
}

// ---------------------------------------------------------------- fp32 -> fp16 convert
__global__ void tofp16_kernel(const float* __restrict__ in, __half* __restrict__ out) {
    int t = blockIdx.x * 256 + threadIdx.x;        // float4 index
    float4 v = ((const float4*)in)[t];
    __half h[4];
    h[0] = __float2half_rn(v.x);  h[1] = __float2half_rn(v.y);
    h[2] = __float2half_rn(v.z);  h[3] = __float2half_rn(v.w);
    ((uint2*)out)[t] = *(uint2*)h;
}

// ---------------------------------------------------------------- weight transpose (fp16)
__global__ void transpose_h(const float* __restrict__ in, int N, int Kt,
                            __half* __restrict__ oh) {
    __shared__ float t[32][33];
    int n0 = blockIdx.x * 32, k0 = blockIdx.y * 32;
    int xx = threadIdx.x;
    for (int j = threadIdx.y; j < 32; j += 8)
        t[j][xx] = in[(size_t)(k0 + j) * N + n0 + xx];
    __syncthreads();
    for (int j = threadIdx.y; j < 32; j += 8)
        oh[(size_t)(n0 + j) * Kt + k0 + xx] = __float2half_rn(t[xx][j]);
}

// ---------------------------------------------------------------- mma.sync GEMM
// CTA tile 128x256, warp tile 64x64 (8 warps: 2M x 4N), BK=32, 3-stage cp.async.
// C = A_fp16[M,K] @ B_fp16^T[N,K]
// MODE 0: C -> fp32                       [Z = x @ W1a]
// MODE 1: relu(C + bias + Sum w_k Z[idx_k]) -> fp16   [layer 1]
// MODE 2: relu(C + bias) -> fp32          [layer 2 -> d_out]
#define A_TILE_B  10240               // 128 rows * 80B (32 fp16 padded to 40)
#define B_TILE_B  20480               // 256 rows * 80B
#define OFF_A     0
#define OFF_B     A_TILE_B
#define STG_B     (A_TILE_B + B_TILE_B)           // 30720
#define NSTG      3
#define GEMM_SMEM (NSTG * STG_B)                  // 92160

template<int MODE>
__global__ __launch_bounds__(256, 1)
void gemm_mma(const __half* __restrict__ A, const __half* __restrict__ B,
              const float* __restrict__ bias, const float* __restrict__ Zt,
              float* __restrict__ outF, __half* __restrict__ outH,
              int K, int ldout) {
    extern __shared__ __align__(128) char smem[];
    const uint32_t sbase = smem_u32(smem);
    const int tid  = threadIdx.x;
    const int wid  = tid >> 5, lane = tid & 31;
    const int wm   = (wid >> 2) * 64;          // warp M offset (0/64)
    const int wn   = (wid & 3) * 64;           // warp N offset (0..192)
    const int bm   = blockIdx.y * 128, bn = blockIdx.x * 256;
    const int KT   = K >> 5;                   // BK=32 tiles

    const int rA = tid >> 2, qA = tid & 3;     // 16B chunk decomposition

    auto load_tile = [&](int kt, int stg) {
        const uint32_t sb = sbase + stg * STG_B;
        const size_t ka = (size_t)kt * 32;
        #pragma unroll
        for (int l = 0; l < 2; l++) {          // A: 128 rows x 4 chunks
            int r = rA + l * 64;
            size_t ar = (size_t)(bm + r) * K + ka + qA * 8;
            cp16(sb + OFF_A + r * 80 + qA * 16, A + ar);
        }
        #pragma unroll
        for (int l = 0; l < 4; l++) {          // B: 256 rows x 4 chunks
            int r = rA + l * 64;
            size_t br = (size_t)(bn + r) * K + ka + qA * 8;
            cp16(sb + OFF_B + r * 80 + qA * 16, B + br);
        }
        asm volatile("cp.async.commit_group;" ::: "memory");
    };

    float acc[4][8][4];
    #pragma unroll
    for (int a = 0; a < 4; a++)
        #pragma unroll
        for (int b = 0; b < 8; b++)
            #pragma unroll
            for (int c = 0; c < 4; c++) acc[a][b][c] = 0.0f;

    const int lmr = (lane & 7) + ((lane >> 3) & 1) * 8;
    const int lmc = (lane >> 4) & 1;

    load_tile(0, 0);
    load_tile(1, 1);

    for (int kt = 0; kt < KT; kt++) {
        asm volatile("cp.async.wait_group 1;" ::: "memory");
        __syncthreads();
        if (kt + 2 < KT) load_tile(kt + 2, (kt + 2) % NSTG);

        const uint32_t sb   = sbase + (kt % NSTG) * STG_B;
        const uint32_t aOff = sb + OFF_A + (wm + lmr) * 80 + lmc * 16;
        const uint32_t bOff = sb + OFF_B + (wn + lmr) * 80 + lmc * 16;

        #pragma unroll
        for (int kc = 0; kc < 2; kc++) {
            uint32_t aR[4][4];
            #pragma unroll
            for (int mt = 0; mt < 4; mt++)
                ldsm4(aR[mt], aOff + mt * 16 * 80 + kc * 32);
            #pragma unroll
            for (int nh = 0; nh < 2; nh++) {
                uint32_t bR[4][2];
                #pragma unroll
                for (int bt = 0; bt < 2; bt++) {
                    uint32_t t4[4];
                    ldsm4(t4, bOff + (nh * 2 + bt) * 16 * 80 + kc * 32);
                    bR[bt * 2][0] = t4[0];     bR[bt * 2][1] = t4[2];
                    bR[bt * 2 + 1][0] = t4[1]; bR[bt * 2 + 1][1] = t4[3];
                }
                #pragma unroll
                for (int mt = 0; mt < 4; mt++)
                    #pragma unroll
                    for (int nt = 0; nt < 4; nt++)
                        mma16816(acc[mt][nh * 4 + nt], aR[mt], bR[nt]);
            }
        }
    }

    // ---------------- epilogue ----------------
    #pragma unroll
    for (int mt = 0; mt < 4; mt++) {
        int r0 = bm + wm + mt * 16 + (lane >> 2);
        int r1 = r0 + 8;
        int   ja0 = 0, ja1 = 0, ja2 = 0, jb0 = 0, jb1 = 0, jb2 = 0;
        float wa0 = 0, wa1 = 0, wa2 = 0, wb0 = 0, wb1 = 0, wb2 = 0;
        if (MODE == 1) {
            ja0 = g_idx[r0 * 3 + 0]; ja1 = g_idx[r0 * 3 + 1]; ja2 = g_idx[r0 * 3 + 2];
            wa0 = g_w[r0 * 3 + 0];   wa1 = g_w[r0 * 3 + 1];   wa2 = g_w[r0 * 3 + 2];
            jb0 = g_idx[r1 * 3 + 0]; jb1 = g_idx[r1 * 3 + 1]; jb2 = g_idx[r1 * 3 + 2];
            wb0 = g_w[r1 * 3 + 0];   wb1 = g_w[r1 * 3 + 1];   wb2 = g_w[r1 * 3 + 2];
        }
        #pragma unroll
        for (int nt = 0; nt < 8; nt++) {
            int c = bn + wn + nt * 8 + (lane & 3) * 2;
            float v0 = acc[mt][nt][0], v1 = acc[mt][nt][1];
            float v2 = acc[mt][nt][2], v3 = acc[mt][nt][3];
            if (MODE != 0) {
                float2 bv = *(const float2*)(bias + c);
                v0 += bv.x; v1 += bv.y; v2 += bv.x; v3 += bv.y;
            }
            if (MODE == 1) {
                float2 z;
                z = *(const float2*)(Zt + (size_t)ja0 * 512 + c); v0 += wa0 * z.x; v1 += wa0 * z.y;
                z = *(const float2*)(Zt + (size_t)ja1 * 512 + c); v0 += wa1 * z.x; v1 += wa1 * z.y;
                z = *(const float2*)(Zt + (size_t)ja2 * 512 + c); v0 += wa2 * z.x; v1 += wa2 * z.y;
                z = *(const float2*)(Zt + (size_t)jb0 * 512 + c); v2 += wb0 * z.x; v3 += wb0 * z.y;
                z = *(const float2*)(Zt + (size_t)jb1 * 512 + c); v2 += wb1 * z.x; v3 += wb1 * z.y;
                z = *(const float2*)(Zt + (size_t)jb2 * 512 + c); v2 += wb2 * z.x; v3 += wb2 * z.y;
            }
            if (MODE != 0) {
                v0 = fmaxf(v0, 0.0f); v1 = fmaxf(v1, 0.0f);
                v2 = fmaxf(v2, 0.0f); v3 = fmaxf(v3, 0.0f);
            }
            if (MODE == 1) {
                *(__half2*)(outH + (size_t)r0 * ldout + c) =
                    __halves2half2(__float2half_rn(v0), __float2half_rn(v1));
                *(__half2*)(outH + (size_t)r1 * ldout + c) =
                    __halves2half2(__float2half_rn(v2), __float2half_rn(v3));
            } else {
                *(float2*)(outF + (size_t)r0 * ldout + c) = make_float2(v0, v1);
                *(float2*)(outF + (size_t)r1 * ldout + c) = make_float2(v2, v3);
            }
        }
    }
}

// ---------------------------------------------------------------- tail
__global__ void tail_kernel(const float* __restrict__ pos_skip,
                            const int* __restrict__ batch_skip,
                            float* __restrict__ out) {
    int t = blockIdx.x * 256 + threadIdx.x;
    const size_t POS_OFF = (size_t)MM * CC;
    const size_t BAT_OFF = POS_OFF + (size_t)MM * 3;
    if (t < MM * 3) out[POS_OFF + t] = pos_skip[t];
    if (t < MM)     out[BAT_OFF + t] = (float)batch_skip[t];
}

// ---------------------------------------------------------------- launch
extern "C" void kernel_launch(void* const* d_in, const int* in_sizes, int n_in,
                              void* d_out, int out_size) {
    const float* x          = (const float*)d_in[0];
    const float* pos        = (const float*)d_in[1];
    const float* x_skip     = (const float*)d_in[3];
    const float* pos_skip   = (const float*)d_in[4];
    const int*   batch_skip = (const int*)d_in[5];
    const float* W1         = (const float*)d_in[6];
    const float* b1         = (const float*)d_in[7];
    const float* W2         = (const float*)d_in[8];
    const float* b2         = (const float*)d_in[9];
    float* out = (float*)d_out;

    __half *Xh, *Sh, *H1h, *W1aT, *W1bT, *W2T;
    float* Z;
    cudaGetSymbolAddress((void**)&Xh, g_Xh);
    cudaGetSymbolAddress((void**)&Sh, g_Sh);
    cudaGetSymbolAddress((void**)&H1h, g_H1h);
    cudaGetSymbolAddress((void**)&W1aT, g_W1aT);
    cudaGetSymbolAddress((void**)&W1bT, g_W1bT);
    cudaGetSymbolAddress((void**)&W2T, g_W2T);
    cudaGetSymbolAddress((void**)&Z, g_Z);

    cudaFuncSetAttribute(gemm_mma<0>, cudaFuncAttributeMaxDynamicSharedMemorySize, GEMM_SMEM);
    cudaFuncSetAttribute(gemm_mma<1>, cudaFuncAttributeMaxDynamicSharedMemorySize, GEMM_SMEM);
    cudaFuncSetAttribute(gemm_mma<2>, cudaFuncAttributeMaxDynamicSharedMemorySize, GEMM_SMEM);

    // 1) KNN + input converts + weight prep
    knn_kernel<<<MM / 256, 256>>>(pos, pos_skip);
    tofp16_kernel<<<MC * 256 / 4 / 256, 256>>>(x, Xh);
    tofp16_kernel<<<MM * 256 / 4 / 256, 256>>>(x_skip, Sh);
    transpose_h<<<dim3(512 / 32, 256 / 32), dim3(32, 8)>>>(W1, 512, 256, W1aT);
    transpose_h<<<dim3(512 / 32, 256 / 32), dim3(32, 8)>>>(W1 + 256 * 512, 512, 256, W1bT);
    transpose_h<<<dim3(256 / 32, 512 / 32), dim3(32, 8)>>>(W2, 256, 512, W2T);

    // 2) Z = x @ W1a            [16384 x 512], K=256
    gemm_mma<0><<<dim3(512 / 256, MC / 128), 256, GEMM_SMEM>>>(
        Xh, W1aT, nullptr, nullptr, Z, nullptr, 256, 512);

    // 3) H1 = relu(x_skip @ W1b + gather(Z) + b1)  [65536 x 512], K=256
    gemm_mma<1><<<dim3(512 / 256, MM / 128), 256, GEMM_SMEM>>>(
        Sh, W1bT, b1, Z, nullptr, H1h, 256, 512);

    // 4) out = relu(H1 @ W2 + b2)                  [65536 x 256], K=512
    gemm_mma<2><<<dim3(256 / 256, MM / 128), 256, GEMM_SMEM>>>(
        H1h, W2T, b2, nullptr, out, nullptr, 512, 256);

    // 5) tail outputs
    const long long FULL = (long long)MM * CC + (long long)MM * 3 + MM;
    if ((long long)out_size >= FULL) {
        tail_kernel<<<(MM * 3 + 255) / 256, 256>>>(pos_skip, batch_skip, out);
    }
}